// round 16
// baseline (speedup 1.0000x reference)
#include <cuda_runtime.h>
#include <cuda_bf16.h>
#include <cuda_fp16.h>
#include <cstdint>
#include <math.h>

#define NB 128   // batch
#define NT 512   // time
#define NF 256   // features
#define NH 512   // hidden
#define NG 2048  // 4*H
#define NBLK 128 // recurrence grid
#define M_TOT (NB * NT)  // 65536

// Scratch (device globals: allocation-free rule)
__device__ float g_xz[(size_t)M_TOT * NG];            // [B*T, 4H]
__device__ __nv_bfloat16 g_xHi[(size_t)M_TOT * NF];   // x bf16 hi
__device__ __nv_bfloat16 g_xLo[(size_t)M_TOT * NF];   // x bf16 lo residual
__device__ uint2 g_wf[262144];                        // W frag-order
// h transposed, pre-swizzled fp16: [par][k=512][b=128], 256B rows,
// 16B unit u at (k,b) stored at u ^ (k&15).  par stride = 131072 bytes.
__device__ __half g_hT[2][NH][NB];
__device__ unsigned g_bar;                            // grid barrier counter

__device__ __forceinline__ void cp16(void* smem_dst, const void* gmem_src) {
    unsigned s = (unsigned)__cvta_generic_to_shared(smem_dst);
    asm volatile("cp.async.cg.shared.global [%0], [%1], 16;" :: "r"(s), "l"(gmem_src));
}
__device__ __forceinline__ void cp_commit() { asm volatile("cp.async.commit_group;"); }
__device__ __forceinline__ void cp_wait0()  { asm volatile("cp.async.wait_group 0;"); }

__device__ __forceinline__ void mma_bf16(float* c, const unsigned* a, uint2 b) {
    asm volatile(
        "mma.sync.aligned.m16n8k16.row.col.f32.bf16.bf16.f32 "
        "{%0,%1,%2,%3},{%4,%5,%6,%7},{%8,%9},{%0,%1,%2,%3};"
        : "+f"(c[0]), "+f"(c[1]), "+f"(c[2]), "+f"(c[3])
        : "r"(a[0]), "r"(a[1]), "r"(a[2]), "r"(a[3]), "r"(b.x), "r"(b.y));
}
__device__ __forceinline__ void mma_f16(float* c, const unsigned* a, uint2 b) {
    asm volatile(
        "mma.sync.aligned.m16n8k16.row.col.f32.f16.f16.f32 "
        "{%0,%1,%2,%3},{%4,%5,%6,%7},{%8,%9},{%0,%1,%2,%3};"
        : "+f"(c[0]), "+f"(c[1]), "+f"(c[2]), "+f"(c[3])
        : "r"(a[0]), "r"(a[1]), "r"(a[2]), "r"(a[3]), "r"(b.x), "r"(b.y));
}
__device__ __forceinline__ void ldmat4(unsigned* a, unsigned saddr) {
    asm volatile("ldmatrix.sync.aligned.m8n8.x4.shared.b16 {%0,%1,%2,%3}, [%4];"
                 : "=r"(a[0]), "=r"(a[1]), "=r"(a[2]), "=r"(a[3]) : "r"(saddr));
}
__device__ __forceinline__ void ldmat4t(unsigned* a, unsigned saddr) {
    asm volatile("ldmatrix.sync.aligned.m8n8.x4.trans.shared.b16 {%0,%1,%2,%3}, [%4];"
                 : "=r"(a[0]), "=r"(a[1]), "=r"(a[2]), "=r"(a[3]) : "r"(saddr));
}
__device__ __forceinline__ void mbar_init(unsigned a, unsigned cnt) {
    asm volatile("mbarrier.init.shared.b64 [%0], %1;" :: "r"(a), "r"(cnt) : "memory");
}
__device__ __forceinline__ void mbar_expect(unsigned a, unsigned tx) {
    asm volatile("mbarrier.arrive.expect_tx.shared.b64 _, [%0], %1;"
                 :: "r"(a), "r"(tx) : "memory");
}
__device__ __forceinline__ void bulk_g2s_mc(unsigned dst, const void* src, unsigned n,
                                            unsigned mbar, unsigned short mask) {
    asm volatile("cp.async.bulk.shared::cluster.global.mbarrier::complete_tx::bytes"
                 ".multicast::cluster [%0], [%1], %2, [%3], %4;"
                 :: "r"(dst), "l"(src), "r"(n), "r"(mbar), "h"(mask) : "memory");
}
__device__ __forceinline__ void mbar_wait(unsigned a, unsigned phase) {
    unsigned done;
    do {
        asm volatile(
            "{\n\t.reg .pred p;\n\t"
            "mbarrier.try_wait.parity.acquire.cta.shared::cta.b64 p, [%1], %2, 0x989680;\n\t"
            "selp.b32 %0, 1, 0, p;\n\t}"
            : "=r"(done) : "r"(a), "r"(phase) : "memory");
    } while (!done);
}
__device__ __forceinline__ unsigned cta_rank() {
    unsigned r; asm("mov.u32 %0, %%cluster_ctarank;" : "=r"(r)); return r;
}
__device__ __forceinline__ void cluster_sync() {
    asm volatile("barrier.cluster.arrive.aligned;" ::: "memory");
    asm volatile("barrier.cluster.wait.aligned;" ::: "memory");
}
__device__ __forceinline__ __nv_bfloat16 bhi(float e) { return __float2bfloat16_rn(e); }
__device__ __forceinline__ __nv_bfloat16 blo(float e) {
    __nv_bfloat16 h = __float2bfloat16_rn(e);
    return __float2bfloat16_rn(e - __bfloat162float(h));
}
// fast gate math: MUFU-based, rel err ~1e-6 (negligible vs fp16 noise)
__device__ __forceinline__ float rcp_fast(float x) {
    float r; asm("rcp.approx.f32 %0, %1;" : "=f"(r) : "f"(x)); return r;
}
__device__ __forceinline__ float sigmoid_fast(float x) {
    return rcp_fast(1.f + __expf(-x));
}
__device__ __forceinline__ float tanh_fast(float x) {
    return 1.f - 2.f * rcp_fast(1.f + __expf(2.f * x));
}

// ---------------------------------------------------------------------------
// Kernel 0: convert x -> bf16 hi/lo, W -> fragment-ordered bf16 hi/lo.
// Also resets the grid barrier counter.
// ---------------------------------------------------------------------------
__global__ __launch_bounds__(256) void conv_kernel(const float* __restrict__ x,
                                                   const float* __restrict__ w) {
    if (blockIdx.x == 0 && threadIdx.x == 0) g_bar = 0u;
    const int tid = blockIdx.x * blockDim.x + threadIdx.x;
    const int nth = gridDim.x * blockDim.x;

    const float4* x4 = (const float4*)x;
    for (size_t i = tid; i < (size_t)M_TOT * NF / 4; i += nth) {
        float4 v = x4[i];
        float e[4] = {v.x, v.y, v.z, v.w};
        __nv_bfloat16 h[4], l[4];
#pragma unroll
        for (int j = 0; j < 4; j++) { h[j] = bhi(e[j]); l[j] = blo(e[j]); }
        ((uint2*)g_xHi)[i] = *(uint2*)h;
        ((uint2*)g_xLo)[i] = *(uint2*)l;
    }

    for (int j = tid; j < 262144; j += nth) {
        int lane = j & 31, n8 = (j >> 5) & 15, k16 = (j >> 9) & 15;
        int nblk = (j >> 13) & 15, term = j >> 17;
        int n = nblk * 128 + n8 * 8 + (lane >> 2);
        int k = k16 * 16 + (lane & 3) * 2;
        float e0 = w[(size_t)k * NG + n];
        float e1 = w[(size_t)(k + 1) * NG + n];
        float e2 = w[(size_t)(k + 8) * NG + n];
        float e3 = w[(size_t)(k + 9) * NG + n];
        __nv_bfloat16 v[4];
        if (term == 0) { v[0] = bhi(e0); v[1] = bhi(e1); v[2] = bhi(e2); v[3] = bhi(e3); }
        else           { v[0] = blo(e0); v[1] = blo(e1); v[2] = blo(e2); v[3] = blo(e3); }
        g_wf[j] = *(uint2*)v;
    }
}

// ---------------------------------------------------------------------------
// Kernel A: xz = x @ W + bias  via bf16 3-term mma.sync. (unchanged)
// ---------------------------------------------------------------------------
__device__ __forceinline__ void xza_stage(char* As, char* Bs, int m0, int nblk,
                                          int tid, int buf, int ks) {
#pragma unroll
    for (int i = 0; i < 8; i++) {
        int f = tid + i * 256;
        int term = f >> 10, rem = f & 1023, m = rem >> 3, s = rem & 7;
        const __nv_bfloat16* src = (term ? g_xLo : g_xHi) + (size_t)(m0 + m) * NF + ks * 64 + s * 8;
        cp16(As + buf * 32768 + term * 16384 + m * 128 + ((s * 16) ^ ((m & 7) << 4)), src);
    }
    const char* wsrc = (const char*)g_wf;
#pragma unroll
    for (int i = 0; i < 8; i++) {
        int f = tid + i * 256;
        int term = f >> 10, q = f & 1023;
        cp16(Bs + buf * 32768 + term * 16384 + q * 16,
             wsrc + term * 1048576 + nblk * 65536 + ks * 16384 + q * 16);
    }
    cp_commit();
}

__global__ __launch_bounds__(256) void xza_kernel(const float* __restrict__ bias) {
    extern __shared__ char sm[];
    char* As = sm;
    char* Bs = sm + 65536;
    const int tid = threadIdx.x, w = tid >> 5, lane = tid & 31;
    const int m0 = blockIdx.y * 128, nblk = blockIdx.x, n0 = nblk * 128;
    const int wm = (w >> 2) * 64, wn = (w & 3) * 32;

    float acc[4][4][4];
#pragma unroll
    for (int mt = 0; mt < 4; mt++)
#pragma unroll
        for (int nt = 0; nt < 4; nt++)
#pragma unroll
            for (int q = 0; q < 4; q++) acc[mt][nt][q] = 0.f;

    xza_stage(As, Bs, m0, nblk, tid, 0, 0);
    const unsigned sA = (unsigned)__cvta_generic_to_shared(As);
    const uint2* Bs2 = (const uint2*)Bs;

    for (int ks = 0; ks < 4; ks++) {
        cp_wait0();
        __syncthreads();
        if (ks + 1 < 4) xza_stage(As, Bs, m0, nblk, tid, (ks + 1) & 1, ks + 1);
        const int buf = ks & 1;
        const unsigned sAb = sA + (unsigned)(buf * 32768);
#pragma unroll
        for (int k16 = 0; k16 < 4; k16++) {
            unsigned aHi[4][4], aLo[4][4];
#pragma unroll
            for (int mt = 0; mt < 4; mt++) {
                int row = wm + mt * 16 + (lane & 15);
                unsigned off = (unsigned)(row * 128 +
                    (((k16 * 32) + ((lane >> 4) * 16)) ^ ((row & 7) << 4)));
                ldmat4(aHi[mt], sAb + off);
                ldmat4(aLo[mt], sAb + 16384u + off);
            }
            uint2 bHi[4], bLo[4];
#pragma unroll
            for (int nt = 0; nt < 4; nt++) {
                int n8 = (w & 3) * 4 + nt;
                bHi[nt] = Bs2[buf * 4096 + k16 * 512 + n8 * 32 + lane];
                bLo[nt] = Bs2[buf * 4096 + 2048 + k16 * 512 + n8 * 32 + lane];
            }
#pragma unroll
            for (int mt = 0; mt < 4; mt++)
#pragma unroll
                for (int nt = 0; nt < 4; nt++) {
                    mma_bf16(acc[mt][nt], aHi[mt], bHi[nt]);
                    mma_bf16(acc[mt][nt], aHi[mt], bLo[nt]);
                    mma_bf16(acc[mt][nt], aLo[mt], bHi[nt]);
                }
        }
    }

#pragma unroll
    for (int nt = 0; nt < 4; nt++) {
        int col = n0 + wn + nt * 8 + (lane & 3) * 2;
        float b0 = __ldg(bias + col), b1 = __ldg(bias + col + 1);
#pragma unroll
        for (int mt = 0; mt < 4; mt++) {
            int row = m0 + wm + mt * 16 + (lane >> 2);
            float2 v0 = make_float2(acc[mt][nt][0] + b0, acc[mt][nt][1] + b1);
            float2 v1 = make_float2(acc[mt][nt][2] + b0, acc[mt][nt][3] + b1);
            *(float2*)&g_xz[(size_t)row * NG + col] = v0;
            *(float2*)&g_xz[(size_t)(row + 8) * NG + col] = v1;
        }
    }
}

// launch-slot alignment helper so ncu's profiled slot lands on lstm_rec_kernel
__global__ void align_kernel() {}

// ---------------------------------------------------------------------------
// Kernel B: persistent LSTM recurrence, fp16 h x fp16 R (hi only), mma.sync.
// 128 blocks x 256 threads, cluster dims (2,1,1), atomic grid barrier.
// H staging: 8 x 16KB chunks; cluster rank 0 issues MULTICAST bulk copies
// (mask 0b11) serving both CTAs; both ranks post expect_tx on their own
// mbarrier ring (phase = (t-1)&1).  Warp-independent waits, no per-chunk
// syncthreads.  Barrier-window overlap for out stores + xz prefetch.
// smem (bytes): Rsf 0..16K | Hs 16K..144K (8x16K) | ps | cs | htmp | mbar
// ---------------------------------------------------------------------------
__global__ __launch_bounds__(256) void lstm_rec_kernel(const float* __restrict__ rker,
                                                       float* __restrict__ out) {
    extern __shared__ char smraw[];
    __half* Rsf = (__half*)smraw;                        // 16KB (hi frag-order)
    char* Hs = smraw + 16384;                            // 8 x 16KB
    float* ps = (float*)(smraw + 147456);                // [16][132] 8448B
    float* cs = (float*)(smraw + 155904);                // [4][128]  2048B
    __half* htmp = (__half*)(smraw + 157952);            // [4][128]  1024B
    const unsigned mbar_s = (unsigned)__cvta_generic_to_shared(smraw + 158976);

    const int tid = threadIdx.x;
    const int blk = blockIdx.x;
    const int w = tid >> 5, lane = tid & 31;
    const unsigned rank = cta_rank();

    if (tid == 0) {
#pragma unroll
        for (int i = 0; i < 8; i++) mbar_init(mbar_s + 8 * i, 1);
    }
    asm volatile("fence.proxy.async.shared::cta;" ::: "memory");

    // ---- one-time: R slice (fp16 hi only) into fragment-ordered smem ----
    for (int i = tid; i < 2048; i += 256) {
        int l = i & 31, nn = (i >> 5) & 1, kk = i >> 6;
        int c = l & 3, n = nn * 8 + (l >> 2);
        int gc = (n >> 2) * NH + blk * 4 + (n & 3);
        int kb = kk * 16 + c * 2;
        __half v[4];
        v[0] = __float2half_rn(rker[(size_t)(kb + 0) * NG + gc]);
        v[1] = __float2half_rn(rker[(size_t)(kb + 1) * NG + gc]);
        v[2] = __float2half_rn(rker[(size_t)(kb + 8) * NG + gc]);
        v[3] = __float2half_rn(rker[(size_t)(kb + 9) * NG + gc]);
        *(uint2*)(Rsf + (size_t)i * 4) = *(uint2*)v;
    }
    for (int i = tid; i < 512; i += 256) cs[i] = 0.f;
    __syncthreads();
    // all mbarriers in both CTAs initialized before any multicast lands
    cluster_sync();

    const uint2* Rf2 = (const uint2*)Rsf;
    const unsigned sHs = (unsigned)__cvta_generic_to_shared(Hs);
    // ldmatrix.trans lane addressing (within 64k x 128b chunk, 256B rows):
    const unsigned kl_part = (unsigned)((((lane >> 4) & 1) * 8 + (lane & 7)));
    const unsigned u_part = (unsigned)(w * 2 + ((lane >> 3) & 1));

    // gate-phase thread mapping: 256 threads = (batch b, col-pair jh)
    const int gb = tid & 127, gjh = tid >> 7;
    const float* xz_base = g_xz + (size_t)gb * NT * NG + blk * 4 + gjh * 2;

    // loop-carried xz prefetch (step 0 loaded here; step t+1 in barrier window)
    float2 xzv[4];
#pragma unroll
    for (int g = 0; g < 4; g++) xzv[g] = *(const float2*)(xz_base + g * NH);

    for (int t = 0; t < NT; t++) {
        if (t > 0) {
            float acc0[4] = {0.f, 0.f, 0.f, 0.f};
            float acc1[4] = {0.f, 0.f, 0.f, 0.f};
            const int par = t & 1;
            const char* hbase = (const char*)&g_hT[par][0][0];
            const unsigned phase = (unsigned)((t - 1) & 1);

            // both ranks post expect_tx; rank 0 issues multicast bulk copies
            if (tid == 0) {
#pragma unroll
                for (int p = 0; p < 8; p++) mbar_expect(mbar_s + 8 * p, 16384u);
                if (rank == 0) {
#pragma unroll
                    for (int p = 0; p < 8; p++)
                        bulk_g2s_mc(sHs + p * 16384u, hbase + p * 16384, 16384u,
                                    mbar_s + 8 * p, (unsigned short)0x3);
                }
            }

            // each warp streams through chunks independently (no block sync)
            for (int ch = 0; ch < 8; ch++) {
                mbar_wait(mbar_s + 8 * ch, phase);
                const unsigned bufS = sHs + (unsigned)(ch * 16384);
#pragma unroll
                for (int kk = 0; kk < 4; kk++) {
                    unsigned kl = (unsigned)(kk * 16) + kl_part;
                    unsigned off = kl * 256 + (((u_part ^ (kl & 15))) << 4);
                    unsigned a[4];
                    ldmat4t(a, bufS + off);
                    const int kkg = ch * 4 + kk;
                    uint2 b0 = Rf2[kkg * 64 + lane];
                    uint2 b1 = Rf2[kkg * 64 + 32 + lane];
                    mma_f16(acc0, a, b0);
                    mma_f16(acc1, a, b1);
                }
            }
            const int g2 = lane >> 2, c2 = lane & 3;
            const int r0 = w * 16 + g2;
            {
                int cb = c2 * 2;
                ps[(cb + 0) * 132 + r0]     = acc0[0];
                ps[(cb + 1) * 132 + r0]     = acc0[1];
                ps[(cb + 0) * 132 + r0 + 8] = acc0[2];
                ps[(cb + 1) * 132 + r0 + 8] = acc0[3];
                cb = 8 + c2 * 2;
                ps[(cb + 0) * 132 + r0]     = acc1[0];
                ps[(cb + 1) * 132 + r0]     = acc1[1];
                ps[(cb + 0) * 132 + r0 + 8] = acc1[2];
                ps[(cb + 1) * 132 + r0 + 8] = acc1[3];
            }
        }
        __syncthreads();

        // gates + state update: 256 threads, each handles 2 hidden cols
        float hv[2], cvv[2];
        {
            const int b = gb;
            float z[4][2];
#pragma unroll
            for (int g = 0; g < 4; g++) { z[g][0] = xzv[g].x; z[g][1] = xzv[g].y; }
            if (t > 0) {
#pragma unroll
                for (int g = 0; g < 4; g++)
#pragma unroll
                    for (int j = 0; j < 2; j++)
                        z[g][j] += ps[(g * 4 + gjh * 2 + j) * 132 + b];
            }
#pragma unroll
            for (int j = 0; j < 2; j++) {
                float iv = sigmoid_fast(z[0][j]);
                float fv = sigmoid_fast(z[1][j]);
                float gv = tanh_fast(z[2][j]);
                float ov = sigmoid_fast(z[3][j]);
                int ci = (gjh * 2 + j) * 128 + b;
                float cc2 = fv * cs[ci] + iv * gv;
                cs[ci] = cc2;
                cvv[j] = cc2;
                hv[j] = ov * tanh_fast(cc2);
            }
            // stage h (fp16) into smem for the vectorized transposed store
            htmp[(gjh * 2 + 0) * 128 + b] = __float2half_rn(hv[0]);
            htmp[(gjh * 2 + 1) * 128 + b] = __float2half_rn(hv[1]);
        }
        __syncthreads();

        if (t < NT - 1) {
            // transposed, pre-swizzled h store: 64 x STG.128
            if (tid < 64) {
                int j = tid >> 4, u = tid & 15;
                int k = blk * 4 + j;
                uint4 v = *(uint4*)&htmp[j * 128 + u * 8];
                int par = (t + 1) & 1;
                char* dst = (char*)&g_hT[par][k][0] + (((unsigned)(u ^ (k & 15))) << 4);
                *(uint4*)dst = v;
            }
            __threadfence();
            __syncthreads();
            // post arrival FIRST, then use the wait window for local work
            if (tid == 0) atomicAdd(&g_bar, 1u);

            // barrier-window work: out stores for t + xz prefetch for t+1
            {
                float2 h2 = make_float2(hv[0], hv[1]);
                *(float2*)(out + ((size_t)gb * NT + t) * NH + blk * 4 + gjh * 2) = h2;
                const float* xzp = xz_base + (size_t)(t + 1) * NG;
#pragma unroll
                for (int g = 0; g < 4; g++) xzv[g] = *(const float2*)(xzp + g * NH);
            }

            if (tid == 0) {
                const unsigned target = (unsigned)NBLK * (unsigned)(t + 1);
                while (*((volatile unsigned*)&g_bar) < target) {}
                __threadfence();
            }
            __syncthreads();
        } else {
            // final step: outputs + h/c finals
            float2 h2 = make_float2(hv[0], hv[1]);
            *(float2*)(out + ((size_t)gb * NT + t) * NH + blk * 4 + gjh * 2) = h2;
            size_t off1 = (size_t)NB * NT * NH;
            *(float2*)(out + off1 + (size_t)gb * NH + blk * 4 + gjh * 2) = h2;
            float2 c2v = make_float2(cvv[0], cvv[1]);
            *(float2*)(out + off1 + (size_t)NB * NH + (size_t)gb * NH + blk * 4 + gjh * 2) = c2v;
        }
    }
    // no CTA may exit while multicast targeting its smem could be in flight
    cluster_sync();
}

// ---------------------------------------------------------------------------
extern "C" void kernel_launch(void* const* d_in, const int* in_sizes, int n_in,
                              void* d_out, int out_size) {
    const float* x    = (const float*)d_in[0];  // [B,T,F]
    const float* w    = (const float*)d_in[1];  // [F,4H]
    const float* rk   = (const float*)d_in[2];  // [H,4H]
    const float* bias = (const float*)d_in[3];  // [4H]
    float* out = (float*)d_out;                 // output | h | c

    cudaFuncSetAttribute(xza_kernel,
                         cudaFuncAttributeMaxDynamicSharedMemorySize, 131072);
    cudaFuncSetAttribute(lstm_rec_kernel,
                         cudaFuncAttributeMaxDynamicSharedMemorySize, 159040);

    conv_kernel<<<2048, 256>>>(x, w);
    xza_kernel<<<dim3(16, 512), 256, 131072>>>(bias);
    align_kernel<<<1, 1>>>();

    cudaLaunchConfig_t cfg = {};
    cfg.gridDim = dim3(NBLK, 1, 1);
    cfg.blockDim = dim3(256, 1, 1);
    cfg.dynamicSmemBytes = 159040;
    cudaLaunchAttribute attrs[1];
    attrs[0].id = cudaLaunchAttributeClusterDimension;
    attrs[0].val.clusterDim.x = 2;
    attrs[0].val.clusterDim.y = 1;
    attrs[0].val.clusterDim.z = 1;
    cfg.attrs = attrs;
    cfg.numAttrs = 1;
    cudaLaunchKernelEx(&cfg, lstm_rec_kernel, rk, out);
}

// round 17
// speedup vs baseline: 1.0988x; 1.0988x over previous
#include <cuda_runtime.h>
#include <cuda_bf16.h>
#include <cuda_fp16.h>
#include <cstdint>
#include <math.h>

#define NB 128   // batch
#define NT 512   // time
#define NF 256   // features
#define NH 512   // hidden
#define NG 2048  // 4*H
#define NBLK 128 // recurrence grid
#define M_TOT (NB * NT)  // 65536

// Scratch (device globals: allocation-free rule)
__device__ float g_xz[(size_t)M_TOT * NG];            // [B*T, 4H]
__device__ __nv_bfloat16 g_xHi[(size_t)M_TOT * NF];   // x bf16 hi
__device__ __nv_bfloat16 g_xLo[(size_t)M_TOT * NF];   // x bf16 lo residual
__device__ uint2 g_wf[262144];                        // W frag-order
// h transposed, pre-swizzled fp16: [par][k=512][b=128], 256B rows,
// 16B unit u at (k,b) stored at u ^ (k&15).  par stride = 131072 bytes.
__device__ __half g_hT[2][NH][NB];
__device__ unsigned g_bar;                            // grid barrier counter

__device__ __forceinline__ void cp16(void* smem_dst, const void* gmem_src) {
    unsigned s = (unsigned)__cvta_generic_to_shared(smem_dst);
    asm volatile("cp.async.cg.shared.global [%0], [%1], 16;" :: "r"(s), "l"(gmem_src));
}
__device__ __forceinline__ void cp_commit() { asm volatile("cp.async.commit_group;"); }
__device__ __forceinline__ void cp_wait0()  { asm volatile("cp.async.wait_group 0;"); }

__device__ __forceinline__ void mma_bf16(float* c, const unsigned* a, uint2 b) {
    asm volatile(
        "mma.sync.aligned.m16n8k16.row.col.f32.bf16.bf16.f32 "
        "{%0,%1,%2,%3},{%4,%5,%6,%7},{%8,%9},{%0,%1,%2,%3};"
        : "+f"(c[0]), "+f"(c[1]), "+f"(c[2]), "+f"(c[3])
        : "r"(a[0]), "r"(a[1]), "r"(a[2]), "r"(a[3]), "r"(b.x), "r"(b.y));
}
__device__ __forceinline__ void mma_f16(float* c, const unsigned* a, uint2 b) {
    asm volatile(
        "mma.sync.aligned.m16n8k16.row.col.f32.f16.f16.f32 "
        "{%0,%1,%2,%3},{%4,%5,%6,%7},{%8,%9},{%0,%1,%2,%3};"
        : "+f"(c[0]), "+f"(c[1]), "+f"(c[2]), "+f"(c[3])
        : "r"(a[0]), "r"(a[1]), "r"(a[2]), "r"(a[3]), "r"(b.x), "r"(b.y));
}
__device__ __forceinline__ void ldmat4(unsigned* a, unsigned saddr) {
    asm volatile("ldmatrix.sync.aligned.m8n8.x4.shared.b16 {%0,%1,%2,%3}, [%4];"
                 : "=r"(a[0]), "=r"(a[1]), "=r"(a[2]), "=r"(a[3]) : "r"(saddr));
}
__device__ __forceinline__ void ldmat4t(unsigned* a, unsigned saddr) {
    asm volatile("ldmatrix.sync.aligned.m8n8.x4.trans.shared.b16 {%0,%1,%2,%3}, [%4];"
                 : "=r"(a[0]), "=r"(a[1]), "=r"(a[2]), "=r"(a[3]) : "r"(saddr));
}
__device__ __forceinline__ void mbar_init(unsigned a, unsigned cnt) {
    asm volatile("mbarrier.init.shared.b64 [%0], %1;" :: "r"(a), "r"(cnt) : "memory");
}
__device__ __forceinline__ void mbar_expect(unsigned a, unsigned tx) {
    asm volatile("mbarrier.arrive.expect_tx.shared.b64 _, [%0], %1;"
                 :: "r"(a), "r"(tx) : "memory");
}
__device__ __forceinline__ void bulk_g2s(unsigned dst, const void* src, unsigned n,
                                         unsigned mbar) {
    asm volatile("cp.async.bulk.shared::cta.global.mbarrier::complete_tx::bytes "
                 "[%0], [%1], %2, [%3];"
                 :: "r"(dst), "l"(src), "r"(n), "r"(mbar) : "memory");
}
__device__ __forceinline__ void mbar_wait(unsigned a, unsigned phase) {
    unsigned done;
    do {
        asm volatile(
            "{\n\t.reg .pred p;\n\t"
            "mbarrier.try_wait.parity.acquire.cta.shared::cta.b64 p, [%1], %2, 0x989680;\n\t"
            "selp.b32 %0, 1, 0, p;\n\t}"
            : "=r"(done) : "r"(a), "r"(phase) : "memory");
    } while (!done);
}
__device__ __forceinline__ __nv_bfloat16 bhi(float e) { return __float2bfloat16_rn(e); }
__device__ __forceinline__ __nv_bfloat16 blo(float e) {
    __nv_bfloat16 h = __float2bfloat16_rn(e);
    return __float2bfloat16_rn(e - __bfloat162float(h));
}
// fast gate math: MUFU-based, rel err ~1e-6 (negligible vs fp16 noise)
__device__ __forceinline__ float rcp_fast(float x) {
    float r; asm("rcp.approx.f32 %0, %1;" : "=f"(r) : "f"(x)); return r;
}
__device__ __forceinline__ float sigmoid_fast(float x) {
    return rcp_fast(1.f + __expf(-x));
}
__device__ __forceinline__ float tanh_fast(float x) {
    return 1.f - 2.f * rcp_fast(1.f + __expf(2.f * x));
}

// ---------------------------------------------------------------------------
// Kernel 0: convert x -> bf16 hi/lo, W -> fragment-ordered bf16 hi/lo.
// Also resets the grid barrier counter.
// ---------------------------------------------------------------------------
__global__ __launch_bounds__(256) void conv_kernel(const float* __restrict__ x,
                                                   const float* __restrict__ w) {
    if (blockIdx.x == 0 && threadIdx.x == 0) g_bar = 0u;
    const int tid = blockIdx.x * blockDim.x + threadIdx.x;
    const int nth = gridDim.x * blockDim.x;

    const float4* x4 = (const float4*)x;
    for (size_t i = tid; i < (size_t)M_TOT * NF / 4; i += nth) {
        float4 v = x4[i];
        float e[4] = {v.x, v.y, v.z, v.w};
        __nv_bfloat16 h[4], l[4];
#pragma unroll
        for (int j = 0; j < 4; j++) { h[j] = bhi(e[j]); l[j] = blo(e[j]); }
        ((uint2*)g_xHi)[i] = *(uint2*)h;
        ((uint2*)g_xLo)[i] = *(uint2*)l;
    }

    for (int j = tid; j < 262144; j += nth) {
        int lane = j & 31, n8 = (j >> 5) & 15, k16 = (j >> 9) & 15;
        int nblk = (j >> 13) & 15, term = j >> 17;
        int n = nblk * 128 + n8 * 8 + (lane >> 2);
        int k = k16 * 16 + (lane & 3) * 2;
        float e0 = w[(size_t)k * NG + n];
        float e1 = w[(size_t)(k + 1) * NG + n];
        float e2 = w[(size_t)(k + 8) * NG + n];
        float e3 = w[(size_t)(k + 9) * NG + n];
        __nv_bfloat16 v[4];
        if (term == 0) { v[0] = bhi(e0); v[1] = bhi(e1); v[2] = bhi(e2); v[3] = bhi(e3); }
        else           { v[0] = blo(e0); v[1] = blo(e1); v[2] = blo(e2); v[3] = blo(e3); }
        g_wf[j] = *(uint2*)v;
    }
}

// ---------------------------------------------------------------------------
// Kernel A: xz = x @ W + bias  via bf16 3-term mma.sync. (unchanged)
// ---------------------------------------------------------------------------
__device__ __forceinline__ void xza_stage(char* As, char* Bs, int m0, int nblk,
                                          int tid, int buf, int ks) {
#pragma unroll
    for (int i = 0; i < 8; i++) {
        int f = tid + i * 256;
        int term = f >> 10, rem = f & 1023, m = rem >> 3, s = rem & 7;
        const __nv_bfloat16* src = (term ? g_xLo : g_xHi) + (size_t)(m0 + m) * NF + ks * 64 + s * 8;
        cp16(As + buf * 32768 + term * 16384 + m * 128 + ((s * 16) ^ ((m & 7) << 4)), src);
    }
    const char* wsrc = (const char*)g_wf;
#pragma unroll
    for (int i = 0; i < 8; i++) {
        int f = tid + i * 256;
        int term = f >> 10, q = f & 1023;
        cp16(Bs + buf * 32768 + term * 16384 + q * 16,
             wsrc + term * 1048576 + nblk * 65536 + ks * 16384 + q * 16);
    }
    cp_commit();
}

__global__ __launch_bounds__(256) void xza_kernel(const float* __restrict__ bias) {
    extern __shared__ char sm[];
    char* As = sm;
    char* Bs = sm + 65536;
    const int tid = threadIdx.x, w = tid >> 5, lane = tid & 31;
    const int m0 = blockIdx.y * 128, nblk = blockIdx.x, n0 = nblk * 128;
    const int wm = (w >> 2) * 64, wn = (w & 3) * 32;

    float acc[4][4][4];
#pragma unroll
    for (int mt = 0; mt < 4; mt++)
#pragma unroll
        for (int nt = 0; nt < 4; nt++)
#pragma unroll
            for (int q = 0; q < 4; q++) acc[mt][nt][q] = 0.f;

    xza_stage(As, Bs, m0, nblk, tid, 0, 0);
    const unsigned sA = (unsigned)__cvta_generic_to_shared(As);
    const uint2* Bs2 = (const uint2*)Bs;

    for (int ks = 0; ks < 4; ks++) {
        cp_wait0();
        __syncthreads();
        if (ks + 1 < 4) xza_stage(As, Bs, m0, nblk, tid, (ks + 1) & 1, ks + 1);
        const int buf = ks & 1;
        const unsigned sAb = sA + (unsigned)(buf * 32768);
#pragma unroll
        for (int k16 = 0; k16 < 4; k16++) {
            unsigned aHi[4][4], aLo[4][4];
#pragma unroll
            for (int mt = 0; mt < 4; mt++) {
                int row = wm + mt * 16 + (lane & 15);
                unsigned off = (unsigned)(row * 128 +
                    (((k16 * 32) + ((lane >> 4) * 16)) ^ ((row & 7) << 4)));
                ldmat4(aHi[mt], sAb + off);
                ldmat4(aLo[mt], sAb + 16384u + off);
            }
            uint2 bHi[4], bLo[4];
#pragma unroll
            for (int nt = 0; nt < 4; nt++) {
                int n8 = (w & 3) * 4 + nt;
                bHi[nt] = Bs2[buf * 4096 + k16 * 512 + n8 * 32 + lane];
                bLo[nt] = Bs2[buf * 4096 + 2048 + k16 * 512 + n8 * 32 + lane];
            }
#pragma unroll
            for (int mt = 0; mt < 4; mt++)
#pragma unroll
                for (int nt = 0; nt < 4; nt++) {
                    mma_bf16(acc[mt][nt], aHi[mt], bHi[nt]);
                    mma_bf16(acc[mt][nt], aHi[mt], bLo[nt]);
                    mma_bf16(acc[mt][nt], aLo[mt], bHi[nt]);
                }
        }
    }

#pragma unroll
    for (int nt = 0; nt < 4; nt++) {
        int col = n0 + wn + nt * 8 + (lane & 3) * 2;
        float b0 = __ldg(bias + col), b1 = __ldg(bias + col + 1);
#pragma unroll
        for (int mt = 0; mt < 4; mt++) {
            int row = m0 + wm + mt * 16 + (lane >> 2);
            float2 v0 = make_float2(acc[mt][nt][0] + b0, acc[mt][nt][1] + b1);
            float2 v1 = make_float2(acc[mt][nt][2] + b0, acc[mt][nt][3] + b1);
            *(float2*)&g_xz[(size_t)row * NG + col] = v0;
            *(float2*)&g_xz[(size_t)(row + 8) * NG + col] = v1;
        }
    }
}

// launch-slot alignment helper so ncu's profiled slot lands on lstm_rec_kernel
__global__ void align_kernel() {}

// ---------------------------------------------------------------------------
// Kernel B: persistent LSTM recurrence, fp16 h x fp16 R (hi only), mma.sync.
// 128 blocks x 256 threads, atomic grid barrier.
// H staging: 8 x 16KB chunks issued by thread 0 after the barrier into an
// 8-buffer mbarrier ring (phase = (t-1)&1).  Warp-independent waits.
// POST-MMA PHASE IS WARP-LOCAL: 4 shfl.bfly(2) give each thread all 4 gates
// for 1 batch row x 2 hidden cols; c state lives in registers; h stored
// directly to pre-swizzled g_hT.  No ps/cs/htmp smem, 2 syncthreads/step.
// smem (bytes): Rsf 0..16K | Hs 16K..144K (8x16K) | mbar
// ---------------------------------------------------------------------------
__global__ __launch_bounds__(256) void lstm_rec_kernel(const float* __restrict__ rker,
                                                       float* __restrict__ out) {
    extern __shared__ char smraw[];
    __half* Rsf = (__half*)smraw;                        // 16KB (hi frag-order)
    char* Hs = smraw + 16384;                            // 8 x 16KB
    const unsigned mbar_s = (unsigned)__cvta_generic_to_shared(smraw + 147456);

    const int tid = threadIdx.x;
    const int blk = blockIdx.x;
    const int w = tid >> 5, lane = tid & 31;
    const int g2 = lane >> 2, c2 = lane & 3;

    if (tid == 0) {
#pragma unroll
        for (int i = 0; i < 8; i++) mbar_init(mbar_s + 8 * i, 1);
    }
    asm volatile("fence.proxy.async.shared::cta;" ::: "memory");

    // ---- one-time: R slice (fp16 hi only) into fragment-ordered smem ----
    for (int i = tid; i < 2048; i += 256) {
        int l = i & 31, nn = (i >> 5) & 1, kk = i >> 6;
        int c = l & 3, n = nn * 8 + (l >> 2);
        int gc = (n >> 2) * NH + blk * 4 + (n & 3);
        int kb = kk * 16 + c * 2;
        __half v[4];
        v[0] = __float2half_rn(rker[(size_t)(kb + 0) * NG + gc]);
        v[1] = __float2half_rn(rker[(size_t)(kb + 1) * NG + gc]);
        v[2] = __float2half_rn(rker[(size_t)(kb + 8) * NG + gc]);
        v[3] = __float2half_rn(rker[(size_t)(kb + 9) * NG + gc]);
        *(uint2*)(Rsf + (size_t)i * 4) = *(uint2*)v;
    }
    __syncthreads();

    const uint2* Rf2 = (const uint2*)Rsf;
    const unsigned sHs = (unsigned)__cvta_generic_to_shared(Hs);
    // ldmatrix.trans lane addressing (within 64k x 128b chunk, 256B rows):
    const unsigned kl_part = (unsigned)((((lane >> 4) & 1) * 8 + (lane & 7)));
    const unsigned u_part = (unsigned)(w * 2 + ((lane >> 3) & 1));

    // warp-local gate mapping: this thread owns 1 batch row x 2 hidden cols
    const bool lowhalf = (c2 < 2);            // keeps rowA, owns gates 0 & 2
    const int row = w * 16 + g2 + (lowhalf ? 0 : 8);   // batch index
    const int jp = (c2 & 1) * 2;              // hidden col pair within block's 4
    const float* xz_base = g_xz + (size_t)row * NT * NG + blk * 4 + jp;
    float creg[2] = {0.f, 0.f};               // c state in registers

    // loop-carried xz prefetch (step 0 here; step t+1 in barrier window)
    float2 xzv[4];
#pragma unroll
    for (int g = 0; g < 4; g++) xzv[g] = *(const float2*)(xz_base + g * NH);

    for (int t = 0; t < NT; t++) {
        // z rec terms for (row, jp+0, jp+1), gates 0..3
        float zr[4][2] = {{0.f,0.f},{0.f,0.f},{0.f,0.f},{0.f,0.f}};

        if (t > 0) {
            float acc0[4] = {0.f, 0.f, 0.f, 0.f};
            float acc1[4] = {0.f, 0.f, 0.f, 0.f};
            const int par = t & 1;
            const char* hbase = (const char*)&g_hT[par][0][0];
            const unsigned phase = (unsigned)((t - 1) & 1);

            // issue ALL 8 chunks up front (data guaranteed by grid barrier)
            if (tid == 0) {
#pragma unroll
                for (int p = 0; p < 8; p++) {
                    unsigned mb = mbar_s + 8 * p;
                    mbar_expect(mb, 16384u);
                    bulk_g2s(sHs + p * 16384u, hbase + p * 16384, 16384u, mb);
                }
            }

            // each warp streams through chunks independently (no block sync)
            for (int ch = 0; ch < 8; ch++) {
                mbar_wait(mbar_s + 8 * ch, phase);
                const unsigned bufS = sHs + (unsigned)(ch * 16384);
#pragma unroll
                for (int kk = 0; kk < 4; kk++) {
                    unsigned kl = (unsigned)(kk * 16) + kl_part;
                    unsigned off = kl * 256 + (((u_part ^ (kl & 15))) << 4);
                    unsigned a[4];
                    ldmat4t(a, bufS + off);
                    const int kkg = ch * 4 + kk;
                    uint2 b0 = Rf2[kkg * 64 + lane];
                    uint2 b1 = Rf2[kkg * 64 + 32 + lane];
                    mma_f16(acc0, a, b0);
                    mma_f16(acc1, a, b1);
                }
            }

            // warp-local fragment exchange: partner lane^2 has the other 2 gates
            float oa0 = lowhalf ? acc0[0] : acc0[2];
            float oa1 = lowhalf ? acc0[1] : acc0[3];
            float ob0 = lowhalf ? acc1[0] : acc1[2];
            float ob1 = lowhalf ? acc1[1] : acc1[3];
            float sa0 = lowhalf ? acc0[2] : acc0[0];
            float sa1 = lowhalf ? acc0[3] : acc0[1];
            float sb0 = lowhalf ? acc1[2] : acc1[0];
            float sb1 = lowhalf ? acc1[3] : acc1[1];
            float ra0 = __shfl_xor_sync(0xffffffffu, sa0, 2);
            float ra1 = __shfl_xor_sync(0xffffffffu, sa1, 2);
            float rb0 = __shfl_xor_sync(0xffffffffu, sb0, 2);
            float rb1 = __shfl_xor_sync(0xffffffffu, sb1, 2);
            // own acc0 -> gate (lowhalf?0:1), own acc1 -> gate (lowhalf?2:3)
            zr[0][0] = lowhalf ? oa0 : ra0;  zr[0][1] = lowhalf ? oa1 : ra1;
            zr[1][0] = lowhalf ? ra0 : oa0;  zr[1][1] = lowhalf ? ra1 : oa1;
            zr[2][0] = lowhalf ? ob0 : rb0;  zr[2][1] = lowhalf ? ob1 : rb1;
            zr[3][0] = lowhalf ? rb0 : ob0;  zr[3][1] = lowhalf ? rb1 : ob1;
        }

        // gates + state update (warp-local, c in registers)
        float hv[2];
#pragma unroll
        for (int j = 0; j < 2; j++) {
            float z0 = (j ? xzv[0].y : xzv[0].x) + zr[0][j];
            float z1 = (j ? xzv[1].y : xzv[1].x) + zr[1][j];
            float z2 = (j ? xzv[2].y : xzv[2].x) + zr[2][j];
            float z3 = (j ? xzv[3].y : xzv[3].x) + zr[3][j];
            float iv = sigmoid_fast(z0);
            float fv = sigmoid_fast(z1);
            float gv = tanh_fast(z2);
            float ov = sigmoid_fast(z3);
            float cc = fv * creg[j] + iv * gv;
            creg[j] = cc;
            hv[j] = ov * tanh_fast(cc);
        }

        if (t < NT - 1) {
            // direct pre-swizzled h store: 2 x STG.16 per thread
            const int par = (t + 1) & 1;
            char* hb = (char*)&g_hT[par][0][0];
            const unsigned u = (unsigned)(row >> 3);
            const unsigned boff = (unsigned)((row & 7) * 2);
#pragma unroll
            for (int j = 0; j < 2; j++) {
                int k = blk * 4 + jp + j;
                *(__half*)(hb + k * 256 + (((u ^ (unsigned)(k & 15))) << 4) + boff) =
                    __float2half_rn(hv[j]);
            }
            __threadfence();
            __syncthreads();
            // post arrival FIRST, then use the wait window for local work
            if (tid == 0) atomicAdd(&g_bar, 1u);

            // barrier-window work: out store for t + xz prefetch for t+1
            {
                float2 h2 = make_float2(hv[0], hv[1]);
                *(float2*)(out + ((size_t)row * NT + t) * NH + blk * 4 + jp) = h2;
                const float* xzp = xz_base + (size_t)(t + 1) * NG;
#pragma unroll
                for (int g = 0; g < 4; g++) xzv[g] = *(const float2*)(xzp + g * NH);
            }

            if (tid == 0) {
                const unsigned target = (unsigned)NBLK * (unsigned)(t + 1);
                while (*((volatile unsigned*)&g_bar) < target) {}
                __threadfence();
            }
            __syncthreads();
        } else {
            // final step: outputs + h/c finals
            float2 h2 = make_float2(hv[0], hv[1]);
            *(float2*)(out + ((size_t)row * NT + t) * NH + blk * 4 + jp) = h2;
            size_t off1 = (size_t)NB * NT * NH;
            *(float2*)(out + off1 + (size_t)row * NH + blk * 4 + jp) = h2;
            float2 c2v = make_float2(creg[0], creg[1]);
            *(float2*)(out + off1 + (size_t)NB * NH + (size_t)row * NH + blk * 4 + jp) = c2v;
        }
    }
}

// ---------------------------------------------------------------------------
extern "C" void kernel_launch(void* const* d_in, const int* in_sizes, int n_in,
                              void* d_out, int out_size) {
    const float* x    = (const float*)d_in[0];  // [B,T,F]
    const float* w    = (const float*)d_in[1];  // [F,4H]
    const float* rk   = (const float*)d_in[2];  // [H,4H]
    const float* bias = (const float*)d_in[3];  // [4H]
    float* out = (float*)d_out;                 // output | h | c

    cudaFuncSetAttribute(xza_kernel,
                         cudaFuncAttributeMaxDynamicSharedMemorySize, 131072);
    cudaFuncSetAttribute(lstm_rec_kernel,
                         cudaFuncAttributeMaxDynamicSharedMemorySize, 147520);

    conv_kernel<<<2048, 256>>>(x, w);
    xza_kernel<<<dim3(16, 512), 256, 131072>>>(bias);
    align_kernel<<<1, 1>>>();
    lstm_rec_kernel<<<NBLK, 256, 147520>>>(rk, out);
}